// round 2
// baseline (speedup 1.0000x reference)
#include <cuda_runtime.h>
#include <math.h>
#include <stdint.h>

// ---------------- problem constants ----------------
#define NN      50000
#define NE      800000
#define IN_DIM  256
#define H1N     4
#define D1N     128
#define C1N     512     // H1*D1
#define H2N     1
#define D2N     256
#define C2N     256     // H2*D2
#define NEG_SLOPE 0.2f

// ---------------- device scratch (no allocs allowed) ----------------
__device__ float    g_h1 [(size_t)NN * C1N];   // linear transform layer1 (pre-agg)
__device__ float    g_out1[(size_t)NN * C1N];  // aggregated layer1 output -> elu -> layer2 input
__device__ float    g_h2 [(size_t)NN * C2N];   // linear transform layer2 (pre-agg)
__device__ float    g_el1[(size_t)NN * H1N];
__device__ float    g_er1[(size_t)NN * H1N];
__device__ unsigned g_m1 [(size_t)NN * H1N];
__device__ float    g_s1 [(size_t)NN * H1N];
__device__ float    g_ee1[(size_t)NE * H1N];
__device__ float    g_el2[(size_t)NN * H2N];
__device__ float    g_er2[(size_t)NN * H2N];
__device__ unsigned g_m2 [(size_t)NN * H2N];
__device__ float    g_s2 [(size_t)NN * H2N];
__device__ float    g_ee2[(size_t)NE * H2N];

// ---------------- helpers ----------------
__device__ __forceinline__ unsigned enc_f(float f) {
    unsigned u = __float_as_uint(f);
    return (u & 0x80000000u) ? ~u : (u | 0x80000000u);
}
__device__ __forceinline__ float dec_f(unsigned u) {
    u = (u & 0x80000000u) ? (u & 0x7fffffffu) : ~u;
    return __uint_as_float(u);
}
#define ENC_NEG_INF 0x007FFFFFu   // enc_f(-inf)

__device__ __forceinline__ void red_add_v4(float* p, float4 v) {
    asm volatile("red.global.add.v4.f32 [%0], {%1,%2,%3,%4};"
                 :: "l"(p), "f"(v.x), "f"(v.y), "f"(v.z), "f"(v.w) : "memory");
}

// ---------------- SIMT fp32 GEMM: C[M,Ncol] = A[M,K] @ B[K,Ncol] ----------------
template<int BM, int BN, int BK, int TM, int TN>
__global__ __launch_bounds__(256)
void sgemm_kernel(int M, int Ncol, int K,
                  const float* __restrict__ A,
                  const float* __restrict__ B,
                  float* __restrict__ C) {
    const int cRow = blockIdx.y;
    const int cCol = blockIdx.x;
    const int threadCol = threadIdx.x % (BN / TN);
    const int threadRow = threadIdx.x / (BN / TN);

    __shared__ float As[BK][BM];
    __shared__ float Bs[BK][BN];

    const float* Aptr = A + (size_t)cRow * BM * K;
    const float* Bptr = B + (size_t)cCol * BN;
    float*       Cptr = C + (size_t)cRow * BM * Ncol + (size_t)cCol * BN;

    const int innerRowA = threadIdx.x / (BK / 4);
    const int innerColA = threadIdx.x % (BK / 4);
    const int strideA   = 256 / (BK / 4);
    const int innerRowB = threadIdx.x / (BN / 4);
    const int innerColB = threadIdx.x % (BN / 4);
    const int strideB   = 256 / (BN / 4);

    const int mBase = cRow * BM;

    float acc[TM * TN];
#pragma unroll
    for (int i = 0; i < TM * TN; i++) acc[i] = 0.f;
    float regM[TM], regN[TN];

    for (int bk = 0; bk < K; bk += BK) {
#pragma unroll
        for (int off = 0; off < BM; off += strideA) {
            int r = innerRowA + off;
            float4 t = make_float4(0.f, 0.f, 0.f, 0.f);
            if (mBase + r < M)
                t = *reinterpret_cast<const float4*>(&Aptr[(size_t)r * K + bk + innerColA * 4]);
            As[innerColA * 4 + 0][r] = t.x;
            As[innerColA * 4 + 1][r] = t.y;
            As[innerColA * 4 + 2][r] = t.z;
            As[innerColA * 4 + 3][r] = t.w;
        }
#pragma unroll
        for (int off = 0; off < BK; off += strideB) {
            int r = innerRowB + off;
            *reinterpret_cast<float4*>(&Bs[r][innerColB * 4]) =
                *reinterpret_cast<const float4*>(&Bptr[(size_t)(bk + r) * Ncol + innerColB * 4]);
        }
        __syncthreads();
#pragma unroll
        for (int k = 0; k < BK; ++k) {
#pragma unroll
            for (int i = 0; i < TM; i++) regM[i] = As[k][threadRow * TM + i];
#pragma unroll
            for (int j = 0; j < TN; j++) regN[j] = Bs[k][threadCol * TN + j];
#pragma unroll
            for (int i = 0; i < TM; i++)
#pragma unroll
                for (int j = 0; j < TN; j++)
                    acc[i * TN + j] += regM[i] * regN[j];
        }
        __syncthreads();
    }

#pragma unroll
    for (int i = 0; i < TM; i++) {
        int r = threadRow * TM + i;
        if (mBase + r < M) {
#pragma unroll
            for (int j = 0; j < TN; j += 4) {
                float4 t = make_float4(acc[i * TN + j], acc[i * TN + j + 1],
                                       acc[i * TN + j + 2], acc[i * TN + j + 3]);
                *reinterpret_cast<float4*>(&Cptr[(size_t)r * Ncol + threadCol * TN + j]) = t;
            }
        }
    }
}

// ---------------- el/er coefficients: warp per (node, head) ----------------
__global__ void attn_coef_kernel(const float* __restrict__ h,
                                 const float* __restrict__ al,
                                 const float* __restrict__ ar,
                                 float* __restrict__ el,
                                 float* __restrict__ er,
                                 int n, int heads, int dim) {
    int warpId = (blockIdx.x * blockDim.x + threadIdx.x) >> 5;
    int lane   = threadIdx.x & 31;
    int total  = n * heads;
    if (warpId >= total) return;
    int node = warpId / heads;
    int hd   = warpId - node * heads;
    const float* hp  = h + (size_t)node * heads * dim + (size_t)hd * dim;
    const float* alp = al + (size_t)hd * dim;
    const float* arp = ar + (size_t)hd * dim;
    float sl = 0.f, sr = 0.f;
    for (int c = lane * 4; c < dim; c += 128) {
        float4 hv = *reinterpret_cast<const float4*>(hp + c);
        float4 av = *reinterpret_cast<const float4*>(alp + c);
        float4 bv = *reinterpret_cast<const float4*>(arp + c);
        sl += hv.x * av.x + hv.y * av.y + hv.z * av.z + hv.w * av.w;
        sr += hv.x * bv.x + hv.y * bv.y + hv.z * bv.z + hv.w * bv.w;
    }
#pragma unroll
    for (int o = 16; o > 0; o >>= 1) {
        sl += __shfl_xor_sync(0xffffffffu, sl, o);
        sr += __shfl_xor_sync(0xffffffffu, sr, o);
    }
    if (lane == 0) { el[warpId] = sl; er[warpId] = sr; }
}

// ---------------- init kernels ----------------
__global__ void init_ms_kernel(unsigned* __restrict__ m, float* __restrict__ s, int n) {
    int i = blockIdx.x * blockDim.x + threadIdx.x;
    if (i < n) { m[i] = ENC_NEG_INF; s[i] = 0.f; }
}

__global__ void zero_kernel(float4* __restrict__ p, int n4) {
    int stride = gridDim.x * blockDim.x;
    for (int i = blockIdx.x * blockDim.x + threadIdx.x; i < n4; i += stride)
        p[i] = make_float4(0.f, 0.f, 0.f, 0.f);
}

// ---------------- edge pass 1: segment max ----------------
template<int H>
__global__ void edge_max_kernel(const int* __restrict__ src,
                                const int* __restrict__ dst,
                                const float* __restrict__ el,
                                const float* __restrict__ er,
                                unsigned* __restrict__ m) {
    int i = blockIdx.x * blockDim.x + threadIdx.x;
    if (i >= NE) return;
    int s = src[i], d = dst[i];
#pragma unroll
    for (int h = 0; h < H; h++) {
        float x = el[s * H + h] + er[d * H + h];
        float e = x >= 0.f ? x : NEG_SLOPE * x;
        atomicMax(&m[d * H + h], enc_f(e));
    }
}

// ---------------- edge pass 2: exp + segment sum ----------------
template<int H>
__global__ void edge_sum_kernel(const int* __restrict__ src,
                                const int* __restrict__ dst,
                                const float* __restrict__ el,
                                const float* __restrict__ er,
                                const unsigned* __restrict__ m,
                                float* __restrict__ sbuf,
                                float* __restrict__ eebuf) {
    int i = blockIdx.x * blockDim.x + threadIdx.x;
    if (i >= NE) return;
    int s = src[i], d = dst[i];
#pragma unroll
    for (int h = 0; h < H; h++) {
        float x = el[s * H + h] + er[d * H + h];
        float e = x >= 0.f ? x : NEG_SLOPE * x;
        float mv = dec_f(m[d * H + h]);
        if (!isfinite(mv)) mv = 0.f;
        float ee = __expf(e - mv);
        eebuf[(size_t)i * H + h] = ee;
        atomicAdd(&sbuf[d * H + h], ee);
    }
}

// ---------------- edge pass 3: weighted scatter (warp per edge) ----------------
template<int H, int D>
__global__ void edge_scatter_kernel(const int* __restrict__ src,
                                    const int* __restrict__ dst,
                                    const float* __restrict__ hsrc,
                                    const float* __restrict__ eebuf,
                                    const float* __restrict__ sbuf,
                                    float* __restrict__ outp) {
    int gwarp = (blockIdx.x * blockDim.x + threadIdx.x) >> 5;
    int lane  = threadIdx.x & 31;
    if (gwarp >= NE) return;
    int s = src[gwarp], d = dst[gwarp];
    const float* hrow = hsrc + (size_t)s * (H * D);
    float*       orow = outp + (size_t)d * (H * D);
#pragma unroll
    for (int c0 = 0; c0 < H * D; c0 += 128) {
        int col = c0 + lane * 4;
        int h   = col / D;
        float alpha = eebuf[(size_t)gwarp * H + h] / (sbuf[d * H + h] + 1e-9f);
        float4 v = *reinterpret_cast<const float4*>(hrow + col);
        float4 w = make_float4(v.x * alpha, v.y * alpha, v.z * alpha, v.w * alpha);
        red_add_v4(orow + col, w);
    }
}

// ---------------- elementwise ELU (in place) ----------------
__global__ void elu_kernel(float4* __restrict__ p, int n4) {
    int stride = gridDim.x * blockDim.x;
    for (int i = blockIdx.x * blockDim.x + threadIdx.x; i < n4; i += stride) {
        float4 v = p[i];
        v.x = v.x > 0.f ? v.x : expm1f(v.x);
        v.y = v.y > 0.f ? v.y : expm1f(v.y);
        v.z = v.z > 0.f ? v.z : expm1f(v.z);
        v.w = v.w > 0.f ? v.w : expm1f(v.w);
        p[i] = v;
    }
}

// ---------------- launch ----------------
extern "C" void kernel_launch(void* const* d_in, const int* in_sizes, int n_in,
                              void* d_out, int out_size) {
    const float* feat = (const float*)d_in[0];
    const int*   src1 = (const int*)d_in[1];
    const int*   dst1 = (const int*)d_in[2];
    const int*   src2 = (const int*)d_in[3];
    const int*   dst2 = (const int*)d_in[4];
    const float* W1   = (const float*)d_in[5];
    const float* al1  = (const float*)d_in[6];
    const float* ar1  = (const float*)d_in[7];
    const float* W2   = (const float*)d_in[8];
    const float* al2  = (const float*)d_in[9];
    const float* ar2  = (const float*)d_in[10];
    float* outp = (float*)d_out;

    float *h1, *out1, *h2, *el1, *er1, *s1, *ee1, *el2, *er2, *s2, *ee2;
    unsigned *m1, *m2;
    cudaGetSymbolAddress((void**)&h1,  g_h1);
    cudaGetSymbolAddress((void**)&out1,g_out1);
    cudaGetSymbolAddress((void**)&h2,  g_h2);
    cudaGetSymbolAddress((void**)&el1, g_el1);
    cudaGetSymbolAddress((void**)&er1, g_er1);
    cudaGetSymbolAddress((void**)&m1,  g_m1);
    cudaGetSymbolAddress((void**)&s1,  g_s1);
    cudaGetSymbolAddress((void**)&ee1, g_ee1);
    cudaGetSymbolAddress((void**)&el2, g_el2);
    cudaGetSymbolAddress((void**)&er2, g_er2);
    cudaGetSymbolAddress((void**)&m2,  g_m2);
    cudaGetSymbolAddress((void**)&s2,  g_s2);
    cudaGetSymbolAddress((void**)&ee2, g_ee2);

    const int TB = 256;
    const int edgeBlocks    = (NE + TB - 1) / TB;          // 3125
    const int scatterBlocks = NE * 32 / TB;                // 100000

    // ---------- layer 1 ----------
    {
        dim3 grid(C1N / 128, (NN + 127) / 128);
        sgemm_kernel<128,128,16,8,8><<<grid, TB>>>(NN, C1N, IN_DIM, feat, W1, h1);
    }
    attn_coef_kernel<<<(NN * H1N * 32 + TB - 1) / TB, TB>>>(h1, al1, ar1, el1, er1, NN, H1N, D1N);
    init_ms_kernel<<<(NN * H1N + TB - 1) / TB, TB>>>(m1, s1, NN * H1N);
    zero_kernel<<<2048, TB>>>((float4*)out1, NN * C1N / 4);
    edge_max_kernel<H1N><<<edgeBlocks, TB>>>(src1, dst1, el1, er1, m1);
    edge_sum_kernel<H1N><<<edgeBlocks, TB>>>(src1, dst1, el1, er1, m1, s1, ee1);
    edge_scatter_kernel<H1N, D1N><<<scatterBlocks, TB>>>(src1, dst1, h1, ee1, s1, out1);
    elu_kernel<<<2048, TB>>>((float4*)out1, NN * C1N / 4);

    // ---------- layer 2 ----------
    {
        dim3 grid(C2N / 128, (NN + 127) / 128);
        sgemm_kernel<128,128,16,8,8><<<grid, TB>>>(NN, C2N, C1N, out1, W2, h2);
    }
    attn_coef_kernel<<<(NN * H2N * 32 + TB - 1) / TB, TB>>>(h2, al2, ar2, el2, er2, NN, H2N, D2N);
    init_ms_kernel<<<(NN * H2N + TB - 1) / TB, TB>>>(m2, s2, NN * H2N);
    zero_kernel<<<2048, TB>>>((float4*)outp, NN * C2N / 4);
    edge_max_kernel<H2N><<<edgeBlocks, TB>>>(src2, dst2, el2, er2, m2);
    edge_sum_kernel<H2N><<<edgeBlocks, TB>>>(src2, dst2, el2, er2, m2, s2, ee2);
    edge_scatter_kernel<H2N, D2N><<<scatterBlocks, TB>>>(src2, dst2, h2, ee2, s2, outp);
}

// round 3
// speedup vs baseline: 1.3947x; 1.3947x over previous
#include <cuda_runtime.h>
#include <math.h>
#include <stdint.h>

// ---------------- problem constants ----------------
#define NN      50000
#define NE      800000
#define IN_DIM  256
#define H1N     4
#define D1N     128
#define C1N     512     // H1*D1
#define H2N     1
#define D2N     256
#define C2N     256     // H2*D2
#define NEG_SLOPE 0.2f

#define SCAN_BS 1024
#define SCAN_NB ((NN + SCAN_BS - 1) / SCAN_BS)   // 49

// ---------------- device scratch (no allocs allowed) ----------------
__device__ float    g_h1 [(size_t)NN * C1N];   // layer1 linear transform (pre-agg)
__device__ float    g_out1[(size_t)NN * C1N];  // layer1 aggregated + elu -> layer2 input
__device__ float    g_h2 [(size_t)NN * C2N];   // layer2 linear transform (pre-agg)
__device__ float    g_el1[(size_t)NN * H1N];
__device__ float    g_er1[(size_t)NN * H1N];
__device__ float    g_el2[(size_t)NN * H2N];
__device__ float    g_er2[(size_t)NN * H2N];
// CSR scratch
__device__ int      g_cnt[NN];
__device__ int      g_part[NN];
__device__ int      g_bsum[64];
__device__ int      g_soff[64];
__device__ int      g_rowptr[NN + 1];
__device__ int      g_cursor[NN];
__device__ int      g_csrc1[NE];
__device__ int      g_csrc2[NE];
__device__ int      g_rowptr2[NN + 1];

// ---------------- SIMT fp32 GEMM: C[M,Ncol] = A[M,K] @ B[K,Ncol] ----------------
template<int BM, int BN, int BK, int TM, int TN>
__global__ __launch_bounds__(256)
void sgemm_kernel(int M, int Ncol, int K,
                  const float* __restrict__ A,
                  const float* __restrict__ B,
                  float* __restrict__ C) {
    const int cRow = blockIdx.y;
    const int cCol = blockIdx.x;
    const int threadCol = threadIdx.x % (BN / TN);
    const int threadRow = threadIdx.x / (BN / TN);

    __shared__ float As[BK][BM];
    __shared__ float Bs[BK][BN];

    const float* Aptr = A + (size_t)cRow * BM * K;
    const float* Bptr = B + (size_t)cCol * BN;
    float*       Cptr = C + (size_t)cRow * BM * Ncol + (size_t)cCol * BN;

    const int innerRowA = threadIdx.x / (BK / 4);
    const int innerColA = threadIdx.x % (BK / 4);
    const int strideA   = 256 / (BK / 4);
    const int innerRowB = threadIdx.x / (BN / 4);
    const int innerColB = threadIdx.x % (BN / 4);
    const int strideB   = 256 / (BN / 4);

    const int mBase = cRow * BM;

    float acc[TM * TN];
#pragma unroll
    for (int i = 0; i < TM * TN; i++) acc[i] = 0.f;
    float regM[TM], regN[TN];

    for (int bk = 0; bk < K; bk += BK) {
#pragma unroll
        for (int off = 0; off < BM; off += strideA) {
            int r = innerRowA + off;
            float4 t = make_float4(0.f, 0.f, 0.f, 0.f);
            if (mBase + r < M)
                t = *reinterpret_cast<const float4*>(&Aptr[(size_t)r * K + bk + innerColA * 4]);
            As[innerColA * 4 + 0][r] = t.x;
            As[innerColA * 4 + 1][r] = t.y;
            As[innerColA * 4 + 2][r] = t.z;
            As[innerColA * 4 + 3][r] = t.w;
        }
#pragma unroll
        for (int off = 0; off < BK; off += strideB) {
            int r = innerRowB + off;
            *reinterpret_cast<float4*>(&Bs[r][innerColB * 4]) =
                *reinterpret_cast<const float4*>(&Bptr[(size_t)(bk + r) * Ncol + innerColB * 4]);
        }
        __syncthreads();
#pragma unroll
        for (int k = 0; k < BK; ++k) {
#pragma unroll
            for (int i = 0; i < TM; i++) regM[i] = As[k][threadRow * TM + i];
#pragma unroll
            for (int j = 0; j < TN; j++) regN[j] = Bs[k][threadCol * TN + j];
#pragma unroll
            for (int i = 0; i < TM; i++)
#pragma unroll
                for (int j = 0; j < TN; j++)
                    acc[i * TN + j] += regM[i] * regN[j];
        }
        __syncthreads();
    }

#pragma unroll
    for (int i = 0; i < TM; i++) {
        int r = threadRow * TM + i;
        if (mBase + r < M) {
#pragma unroll
            for (int j = 0; j < TN; j += 4) {
                float4 t = make_float4(acc[i * TN + j], acc[i * TN + j + 1],
                                       acc[i * TN + j + 2], acc[i * TN + j + 3]);
                *reinterpret_cast<float4*>(&Cptr[(size_t)r * Ncol + threadCol * TN + j]) = t;
            }
        }
    }
}

// ---------------- el/er coefficients: warp per (node, head) ----------------
__global__ void attn_coef_kernel(const float* __restrict__ h,
                                 const float* __restrict__ al,
                                 const float* __restrict__ ar,
                                 float* __restrict__ el,
                                 float* __restrict__ er,
                                 int n, int heads, int dim) {
    int warpId = (blockIdx.x * blockDim.x + threadIdx.x) >> 5;
    int lane   = threadIdx.x & 31;
    int total  = n * heads;
    if (warpId >= total) return;
    int node = warpId / heads;
    int hd   = warpId - node * heads;
    const float* hp  = h + (size_t)node * heads * dim + (size_t)hd * dim;
    const float* alp = al + (size_t)hd * dim;
    const float* arp = ar + (size_t)hd * dim;
    float sl = 0.f, sr = 0.f;
    for (int c = lane * 4; c < dim; c += 128) {
        float4 hv = *reinterpret_cast<const float4*>(hp + c);
        float4 av = *reinterpret_cast<const float4*>(alp + c);
        float4 bv = *reinterpret_cast<const float4*>(arp + c);
        sl += hv.x * av.x + hv.y * av.y + hv.z * av.z + hv.w * av.w;
        sr += hv.x * bv.x + hv.y * bv.y + hv.z * bv.z + hv.w * bv.w;
    }
#pragma unroll
    for (int o = 16; o > 0; o >>= 1) {
        sl += __shfl_xor_sync(0xffffffffu, sl, o);
        sr += __shfl_xor_sync(0xffffffffu, sr, o);
    }
    if (lane == 0) { el[warpId] = sl; er[warpId] = sr; }
}

// ---------------- CSR build ----------------
__global__ void zero_int_kernel(int* __restrict__ p, int n) {
    int i = blockIdx.x * blockDim.x + threadIdx.x;
    if (i < n) p[i] = 0;
}

__global__ void hist_kernel(const int* __restrict__ dst, int* __restrict__ cnt) {
    int i = blockIdx.x * blockDim.x + threadIdx.x;
    if (i < NE) atomicAdd(&cnt[dst[i]], 1);
}

__global__ __launch_bounds__(SCAN_BS)
void scan_part_kernel(const int* __restrict__ cnt, int* __restrict__ part,
                      int* __restrict__ bsum) {
    __shared__ int sm[SCAN_BS];
    int tid = threadIdx.x;
    int gi = blockIdx.x * SCAN_BS + tid;
    int x = (gi < NN) ? cnt[gi] : 0;
    sm[tid] = x;
    __syncthreads();
#pragma unroll
    for (int off = 1; off < SCAN_BS; off <<= 1) {
        int v = (tid >= off) ? sm[tid - off] : 0;
        __syncthreads();
        sm[tid] += v;
        __syncthreads();
    }
    if (gi < NN) part[gi] = sm[tid] - x;  // exclusive
    if (tid == SCAN_BS - 1) bsum[blockIdx.x] = sm[tid];
}

__global__ void scan_sums_kernel(const int* __restrict__ bsum, int* __restrict__ soff) {
    __shared__ int sm[64];
    int tid = threadIdx.x;  // 64 threads
    int x = (tid < SCAN_NB) ? bsum[tid] : 0;
    sm[tid] = x;
    __syncthreads();
#pragma unroll
    for (int off = 1; off < 64; off <<= 1) {
        int v = (tid >= off) ? sm[tid - off] : 0;
        __syncthreads();
        sm[tid] += v;
        __syncthreads();
    }
    soff[tid] = sm[tid] - x;  // exclusive
}

__global__ void finalize_rowptr_kernel(const int* __restrict__ part,
                                       const int* __restrict__ soff,
                                       int* __restrict__ rowptr,
                                       int* __restrict__ cursor) {
    int i = blockIdx.x * blockDim.x + threadIdx.x;
    if (i < NN) {
        int v = part[i] + soff[i / SCAN_BS];
        rowptr[i] = v;
        cursor[i] = v;
    }
    if (i == 0) rowptr[NN] = NE;
}

__global__ void fill_csr_kernel(const int* __restrict__ src, const int* __restrict__ dst,
                                int* __restrict__ cursor, int* __restrict__ csrc) {
    int i = blockIdx.x * blockDim.x + threadIdx.x;
    if (i >= NE) return;
    int pos = atomicAdd(&cursor[dst[i]], 1);
    csrc[pos] = src[i];
}

// ---------------- fused softmax + aggregation: one block per dst node ----------------
// TPB threads, each owns one float4 (TPB*4 == H*D)
template<int H, int D, int TPB, bool ELU>
__global__ __launch_bounds__(TPB)
void agg_kernel(const int* __restrict__ rowptr,
                const int* __restrict__ csrc,
                const float* __restrict__ hsrc,
                const float* __restrict__ el,
                const float* __restrict__ er,
                float* __restrict__ outp) {
    const int n   = blockIdx.x;
    const int tid = threadIdx.x;
    const int lane = tid & 31;
    const int wid  = tid >> 5;
    constexpr int NW = TPB / 32;

    const int base = rowptr[n];
    const int deg  = rowptr[n + 1] - base;

    __shared__ float sm_er[H];
    __shared__ float sm_m[H];
    __shared__ float sm_inv[H];
    __shared__ float wred[NW][H];

    if (tid < H) sm_er[tid] = er[(size_t)n * H + tid];
    __syncthreads();

    if (deg == 0) {
        float4 z = make_float4(0.f, 0.f, 0.f, 0.f);
        *reinterpret_cast<float4*>(&outp[(size_t)n * (H * D) + tid * 4]) = z;
        return;
    }

    // ---- pass A: per-head max ----
    float lm[H];
#pragma unroll
    for (int h = 0; h < H; h++) lm[h] = -INFINITY;
    for (int j = tid; j < deg; j += TPB) {
        int s = csrc[base + j];
#pragma unroll
        for (int h = 0; h < H; h++) {
            float x = el[(size_t)s * H + h] + sm_er[h];
            float e = x >= 0.f ? x : NEG_SLOPE * x;
            lm[h] = fmaxf(lm[h], e);
        }
    }
#pragma unroll
    for (int h = 0; h < H; h++) {
#pragma unroll
        for (int o = 16; o > 0; o >>= 1)
            lm[h] = fmaxf(lm[h], __shfl_xor_sync(0xffffffffu, lm[h], o));
        if (lane == 0) wred[wid][h] = lm[h];
    }
    __syncthreads();
    if (tid == 0) {
#pragma unroll
        for (int h = 0; h < H; h++) {
            float m = wred[0][h];
#pragma unroll
            for (int w = 1; w < NW; w++) m = fmaxf(m, wred[w][h]);
            sm_m[h] = m;
        }
    }
    __syncthreads();

    // ---- pass B: per-head sum of exp ----
    float ls[H];
#pragma unroll
    for (int h = 0; h < H; h++) ls[h] = 0.f;
    for (int j = tid; j < deg; j += TPB) {
        int s = csrc[base + j];
#pragma unroll
        for (int h = 0; h < H; h++) {
            float x = el[(size_t)s * H + h] + sm_er[h];
            float e = x >= 0.f ? x : NEG_SLOPE * x;
            ls[h] += __expf(e - sm_m[h]);
        }
    }
#pragma unroll
    for (int h = 0; h < H; h++) {
#pragma unroll
        for (int o = 16; o > 0; o >>= 1)
            ls[h] += __shfl_xor_sync(0xffffffffu, ls[h], o);
        if (lane == 0) wred[wid][h] = ls[h];
    }
    __syncthreads();
    if (tid == 0) {
#pragma unroll
        for (int h = 0; h < H; h++) {
            float s = 0.f;
#pragma unroll
            for (int w = 0; w < NW; w++) s += wred[w][h];
            sm_inv[h] = 1.f / (s + 1e-9f);
        }
    }
    __syncthreads();

    // ---- pass C: weighted gather-accumulate ----
    const int col  = tid * 4;
    const int head = col / D;                  // warp-uniform
    const float m_h   = sm_m[head];
    const float inv_h = sm_inv[head];
    const float er_h  = sm_er[head];

    float4 acc = make_float4(0.f, 0.f, 0.f, 0.f);
    for (int j = 0; j < deg; j++) {
        int s = csrc[base + j];                // broadcast
        float x = el[(size_t)s * H + head] + er_h;
        float e = x >= 0.f ? x : NEG_SLOPE * x;
        float alpha = __expf(e - m_h) * inv_h;
        float4 v = *reinterpret_cast<const float4*>(&hsrc[(size_t)s * (H * D) + col]);
        acc.x += v.x * alpha;
        acc.y += v.y * alpha;
        acc.z += v.z * alpha;
        acc.w += v.w * alpha;
    }

    if (ELU) {
        acc.x = acc.x > 0.f ? acc.x : expm1f(acc.x);
        acc.y = acc.y > 0.f ? acc.y : expm1f(acc.y);
        acc.z = acc.z > 0.f ? acc.z : expm1f(acc.z);
        acc.w = acc.w > 0.f ? acc.w : expm1f(acc.w);
    }
    *reinterpret_cast<float4*>(&outp[(size_t)n * (H * D) + col]) = acc;
}

// ---------------- launch ----------------
static void build_csr(const int* src, const int* dst,
                      int* cnt, int* part, int* bsum, int* soff,
                      int* rowptr, int* cursor, int* csrc) {
    const int TB = 256;
    zero_int_kernel<<<(NN + TB - 1) / TB, TB>>>(cnt, NN);
    hist_kernel<<<(NE + TB - 1) / TB, TB>>>(dst, cnt);
    scan_part_kernel<<<SCAN_NB, SCAN_BS>>>(cnt, part, bsum);
    scan_sums_kernel<<<1, 64>>>(bsum, soff);
    finalize_rowptr_kernel<<<(NN + TB - 1) / TB, TB>>>(part, soff, rowptr, cursor);
    fill_csr_kernel<<<(NE + TB - 1) / TB, TB>>>(src, dst, cursor, csrc);
}

extern "C" void kernel_launch(void* const* d_in, const int* in_sizes, int n_in,
                              void* d_out, int out_size) {
    const float* feat = (const float*)d_in[0];
    const int*   src1 = (const int*)d_in[1];
    const int*   dst1 = (const int*)d_in[2];
    const int*   src2 = (const int*)d_in[3];
    const int*   dst2 = (const int*)d_in[4];
    const float* W1   = (const float*)d_in[5];
    const float* al1  = (const float*)d_in[6];
    const float* ar1  = (const float*)d_in[7];
    const float* W2   = (const float*)d_in[8];
    const float* al2  = (const float*)d_in[9];
    const float* ar2  = (const float*)d_in[10];
    float* outp = (float*)d_out;

    float *h1, *out1, *h2, *el1, *er1, *el2, *er2;
    int *cnt, *part, *bsum, *soff, *rowptr, *cursor, *csrc1, *csrc2, *rowptr2;
    cudaGetSymbolAddress((void**)&h1,   g_h1);
    cudaGetSymbolAddress((void**)&out1, g_out1);
    cudaGetSymbolAddress((void**)&h2,   g_h2);
    cudaGetSymbolAddress((void**)&el1,  g_el1);
    cudaGetSymbolAddress((void**)&er1,  g_er1);
    cudaGetSymbolAddress((void**)&el2,  g_el2);
    cudaGetSymbolAddress((void**)&er2,  g_er2);
    cudaGetSymbolAddress((void**)&cnt,    g_cnt);
    cudaGetSymbolAddress((void**)&part,   g_part);
    cudaGetSymbolAddress((void**)&bsum,   g_bsum);
    cudaGetSymbolAddress((void**)&soff,   g_soff);
    cudaGetSymbolAddress((void**)&rowptr, g_rowptr);
    cudaGetSymbolAddress((void**)&cursor, g_cursor);
    cudaGetSymbolAddress((void**)&csrc1,  g_csrc1);
    cudaGetSymbolAddress((void**)&csrc2,  g_csrc2);
    cudaGetSymbolAddress((void**)&rowptr2, g_rowptr2);

    const int TB = 256;

    // ---------- layer 1 ----------
    {
        dim3 grid(C1N / 128, (NN + 127) / 128);
        sgemm_kernel<128,128,16,8,8><<<grid, TB>>>(NN, C1N, IN_DIM, feat, W1, h1);
    }
    attn_coef_kernel<<<(NN * H1N * 32 + TB - 1) / TB, TB>>>(h1, al1, ar1, el1, er1, NN, H1N, D1N);
    build_csr(src1, dst1, cnt, part, bsum, soff, rowptr, cursor, csrc1);
    agg_kernel<H1N, D1N, 128, true><<<NN, 128>>>(rowptr, csrc1, h1, el1, er1, out1);

    // ---------- layer 2 ----------
    {
        dim3 grid(C2N / 128, (NN + 127) / 128);
        sgemm_kernel<128,128,16,8,8><<<grid, TB>>>(NN, C2N, C1N, out1, W2, h2);
    }
    attn_coef_kernel<<<(NN * H2N * 32 + TB - 1) / TB, TB>>>(h2, al2, ar2, el2, er2, NN, H2N, D2N);
    build_csr(src2, dst2, cnt, part, bsum, soff, rowptr2, cursor, csrc2);
    agg_kernel<H2N, D2N, 64, false><<<NN, 64>>>(rowptr2, csrc2, h2, el2, er2, outp);
}